// round 5
// baseline (speedup 1.0000x reference)
#include <cuda_runtime.h>

// Problem constants
#define NUM_U    4
#define NUM_NT   8
#define NPER     (128 * 49152)        // elements per user = 6,291,456
#define N4       (NPER / 4)           // float4 elements per user = 1,572,864
#define THREADS  256
#define IPT      4                    // float4 positions per thread
#define GRID     (N4 / (THREADS * IPT))   // 1536 blocks, exact cover

// out[u,i] = sum_v A[u][v] * x[v,i] + S[u] * noise[u,i]
__global__ __launch_bounds__(THREADS)
void fused_miso_kernel(const float4* __restrict__ x,      // [U][N4]
                       const float4* __restrict__ noise,  // [U][N4]
                       float4* __restrict__ out,          // [U][N4]
                       const float* __restrict__ W,       // [NT, U]
                       const float* __restrict__ H,       // [NT, U]
                       const float* __restrict__ P,       // [U]
                       const float* __restrict__ stddev)  // [U]
{
    __shared__ float sG[NUM_U * NUM_U];
    __shared__ float sA[NUM_U * NUM_U];
    __shared__ float sS[NUM_U];

    const int t = threadIdx.x;

    // ---- per-block coefficient computation (16 threads, ~200 cycles) ----
    if (t < NUM_U * NUM_U) {
        const int u = t >> 2, v = t & 3;
        float acc = 0.f;
        #pragma unroll
        for (int n = 0; n < NUM_NT; n++)
            acc += H[n * NUM_U + u] * W[n * NUM_U + v];
        sG[t] = acc;
    }
    __syncthreads();
    if (t < NUM_U * NUM_U) {
        const int u = t >> 2, v = t & 3;
        const float inv_amp = 1.0f / (sqrtf(P[u]) * sG[u * NUM_U + u]);
        sA[t] = sqrtf(P[v]) * sG[t] * inv_amp;
        if (v == 0) sS[u] = stddev[u] * inv_amp;
    }
    __syncthreads();

    float a[NUM_U * NUM_U];
    #pragma unroll
    for (int k = 0; k < NUM_U * NUM_U; k++) a[k] = sA[k];
    float s[NUM_U];
    #pragma unroll
    for (int u = 0; u < NUM_U; u++) s[u] = sS[u];

    // ---- streaming main loop: exact-cover, fully unrolled ----
    const unsigned total = GRID * THREADS;                  // 393,216
    const unsigned i0 = blockIdx.x * THREADS + t;

    #pragma unroll
    for (int k = 0; k < IPT; k++) {
        const unsigned i = i0 + (unsigned)k * total;        // < N4 always

        // Front-batch the 4 x-loads (streaming, evict-first).
        float4 xv[NUM_U];
        #pragma unroll
        for (int v = 0; v < NUM_U; v++)
            xv[v] = __ldcs(&x[v * (unsigned)N4 + i]);

        // Noise load -> compute -> store per user (keeps live regs low,
        // still 5+ loads in flight at any point).
        #pragma unroll
        for (int u = 0; u < NUM_U; u++) {
            const float4 nv = __ldcs(&noise[u * (unsigned)N4 + i]);
            const float a0 = a[u*NUM_U+0], a1 = a[u*NUM_U+1],
                        a2 = a[u*NUM_U+2], a3 = a[u*NUM_U+3];
            float4 o;
            o.x = fmaf(s[u], nv.x, fmaf(a0, xv[0].x, fmaf(a1, xv[1].x, fmaf(a2, xv[2].x, a3 * xv[3].x))));
            o.y = fmaf(s[u], nv.y, fmaf(a0, xv[0].y, fmaf(a1, xv[1].y, fmaf(a2, xv[2].y, a3 * xv[3].y))));
            o.z = fmaf(s[u], nv.z, fmaf(a0, xv[0].z, fmaf(a1, xv[1].z, fmaf(a2, xv[2].z, a3 * xv[3].z))));
            o.w = fmaf(s[u], nv.w, fmaf(a0, xv[0].w, fmaf(a1, xv[1].w, fmaf(a2, xv[2].w, a3 * xv[3].w))));
            __stcs(&out[u * (unsigned)N4 + i], o);
        }
    }
}

extern "C" void kernel_launch(void* const* d_in, const int* in_sizes, int n_in,
                              void* d_out, int out_size)
{
    // Input order per reference setup_inputs(): x, W, H, P, stddev, noise
    const float* x      = (const float*)d_in[0];
    const float* W      = (const float*)d_in[1];
    const float* H      = (const float*)d_in[2];
    const float* P      = (const float*)d_in[3];
    const float* stddev = (const float*)d_in[4];
    const float* noise  = (const float*)d_in[5];
    float* out = (float*)d_out;

    fused_miso_kernel<<<GRID, THREADS>>>(
        (const float4*)x, (const float4*)noise, (float4*)out,
        W, H, P, stddev);
}

// round 6
// speedup vs baseline: 1.0936x; 1.0936x over previous
#include <cuda_runtime.h>

// Problem constants
#define NUM_U    4
#define NUM_NT   8
#define NPER     (128 * 49152)        // elements per user = 6,291,456
#define N4       (NPER / 4)           // float4 elements per user = 1,572,864
#define THREADS  256
#define IPT      4                    // float4 positions per thread
#define GRID     (N4 / (THREADS * IPT))   // 1536 blocks, exact cover

// out[u,i] = sum_v A[u][v] * x[v,i] + S[u] * noise[u,i]
__global__ __launch_bounds__(THREADS)
void fused_miso_kernel(const float4* __restrict__ x,      // [U][N4]
                       const float4* __restrict__ noise,  // [U][N4]
                       float4* __restrict__ out,          // [U][N4]
                       const float* __restrict__ W,       // [NT, U]
                       const float* __restrict__ H,       // [NT, U]
                       const float* __restrict__ P,       // [U]
                       const float* __restrict__ stddev)  // [U]
{
    __shared__ float sG[NUM_U * NUM_U];
    __shared__ float sA[NUM_U * NUM_U];
    __shared__ float sS[NUM_U];

    const int t = threadIdx.x;

    // ---- per-block coefficient computation (16 threads, ~200 cycles) ----
    if (t < NUM_U * NUM_U) {
        const int u = t >> 2, v = t & 3;
        float acc = 0.f;
        #pragma unroll
        for (int n = 0; n < NUM_NT; n++)
            acc += H[n * NUM_U + u] * W[n * NUM_U + v];
        sG[t] = acc;
    }
    __syncthreads();
    if (t < NUM_U * NUM_U) {
        const int u = t >> 2, v = t & 3;
        const float inv_amp = 1.0f / (sqrtf(P[u]) * sG[u * NUM_U + u]);
        sA[t] = sqrtf(P[v]) * sG[t] * inv_amp;
        if (v == 0) sS[u] = stddev[u] * inv_amp;
    }
    __syncthreads();

    float a[NUM_U * NUM_U];
    #pragma unroll
    for (int k = 0; k < NUM_U * NUM_U; k++) a[k] = sA[k];
    float s[NUM_U];
    #pragma unroll
    for (int u = 0; u < NUM_U; u++) s[u] = sS[u];

    // ---- streaming main loop: exact-cover, loads batched across PAIRS of
    //      positions -> 16 outstanding float4 loads before any FMA/store ----
    const unsigned total = GRID * THREADS;                  // 393,216
    const unsigned i0 = blockIdx.x * THREADS + t;

    #pragma unroll
    for (int p = 0; p < IPT / 2; p++) {
        const unsigned iA = i0 + (unsigned)(2 * p)     * total;  // < N4
        const unsigned iB = i0 + (unsigned)(2 * p + 1) * total;  // < N4

        // Front-batch ALL 16 loads (streaming, evict-first).
        float4 xvA[NUM_U], nvA[NUM_U];
        float4 xvB[NUM_U], nvB[NUM_U];
        #pragma unroll
        for (int v = 0; v < NUM_U; v++) xvA[v] = __ldcs(&x[v * (unsigned)N4 + iA]);
        #pragma unroll
        for (int v = 0; v < NUM_U; v++) xvB[v] = __ldcs(&x[v * (unsigned)N4 + iB]);
        #pragma unroll
        for (int u = 0; u < NUM_U; u++) nvA[u] = __ldcs(&noise[u * (unsigned)N4 + iA]);
        #pragma unroll
        for (int u = 0; u < NUM_U; u++) nvB[u] = __ldcs(&noise[u * (unsigned)N4 + iB]);

        // Compute + store position A, then position B.
        #pragma unroll
        for (int u = 0; u < NUM_U; u++) {
            const float a0 = a[u*NUM_U+0], a1 = a[u*NUM_U+1],
                        a2 = a[u*NUM_U+2], a3 = a[u*NUM_U+3];
            float4 o;
            o.x = fmaf(s[u], nvA[u].x, fmaf(a0, xvA[0].x, fmaf(a1, xvA[1].x, fmaf(a2, xvA[2].x, a3 * xvA[3].x))));
            o.y = fmaf(s[u], nvA[u].y, fmaf(a0, xvA[0].y, fmaf(a1, xvA[1].y, fmaf(a2, xvA[2].y, a3 * xvA[3].y))));
            o.z = fmaf(s[u], nvA[u].z, fmaf(a0, xvA[0].z, fmaf(a1, xvA[1].z, fmaf(a2, xvA[2].z, a3 * xvA[3].z))));
            o.w = fmaf(s[u], nvA[u].w, fmaf(a0, xvA[0].w, fmaf(a1, xvA[1].w, fmaf(a2, xvA[2].w, a3 * xvA[3].w))));
            __stcs(&out[u * (unsigned)N4 + iA], o);
        }
        #pragma unroll
        for (int u = 0; u < NUM_U; u++) {
            const float a0 = a[u*NUM_U+0], a1 = a[u*NUM_U+1],
                        a2 = a[u*NUM_U+2], a3 = a[u*NUM_U+3];
            float4 o;
            o.x = fmaf(s[u], nvB[u].x, fmaf(a0, xvB[0].x, fmaf(a1, xvB[1].x, fmaf(a2, xvB[2].x, a3 * xvB[3].x))));
            o.y = fmaf(s[u], nvB[u].y, fmaf(a0, xvB[0].y, fmaf(a1, xvB[1].y, fmaf(a2, xvB[2].y, a3 * xvB[3].y))));
            o.z = fmaf(s[u], nvB[u].z, fmaf(a0, xvB[0].z, fmaf(a1, xvB[1].z, fmaf(a2, xvB[2].z, a3 * xvB[3].z))));
            o.w = fmaf(s[u], nvB[u].w, fmaf(a0, xvB[0].w, fmaf(a1, xvB[1].w, fmaf(a2, xvB[2].w, a3 * xvB[3].w))));
            __stcs(&out[u * (unsigned)N4 + iB], o);
        }
    }
}

extern "C" void kernel_launch(void* const* d_in, const int* in_sizes, int n_in,
                              void* d_out, int out_size)
{
    // Input order per reference setup_inputs(): x, W, H, P, stddev, noise
    const float* x      = (const float*)d_in[0];
    const float* W      = (const float*)d_in[1];
    const float* H      = (const float*)d_in[2];
    const float* P      = (const float*)d_in[3];
    const float* stddev = (const float*)d_in[4];
    const float* noise  = (const float*)d_in[5];
    float* out = (float*)d_out;

    fused_miso_kernel<<<GRID, THREADS>>>(
        (const float4*)x, (const float4*)noise, (float4*)out,
        W, H, P, stddev);
}